// round 5
// baseline (speedup 1.0000x reference)
#include <cuda_runtime.h>

// Sigma = Q diag(exp(2*log_s)) Q^T, normalization folded in (inv = 2/|q|^2).
// Persistent grid-stride kernel, warp-private smem staging, register prefetch
// of next tile's gmem loads to overlap DRAM latency with compute+stores.

#define BLK   256
#define WARPS (BLK / 32)

__device__ __forceinline__ void compute_sigma(float w, float x, float y, float z,
                                              float s0, float s1, float s2,
                                              float* r /*6 outs*/)
{
    float n2  = fmaf(w, w, fmaf(x, x, fmaf(y, y, z * z)));
    float inv = __fdividef(2.0f, n2);

    float xx = x * x, yy = y * y, zz = z * z;
    float xy = x * y, xz = x * z, yz = y * z;
    float wx = w * x, wy = w * y, wz = w * z;

    float r00 = 1.0f - inv * (yy + zz);
    float r01 = inv * (xy - wz);
    float r02 = inv * (xz + wy);
    float r10 = inv * (xy + wz);
    float r11 = 1.0f - inv * (xx + zz);
    float r12 = inv * (yz - wx);
    float r20 = inv * (xz - wy);
    float r21 = inv * (yz + wx);
    float r22 = 1.0f - inv * (xx + yy);

    float a0 = s0 * r00, a1 = s1 * r01, a2 = s2 * r02;
    float b0 = s0 * r10, b1 = s1 * r11, b2 = s2 * r12;
    float c0 = s0 * r20, c1 = s1 * r21, c2 = s2 * r22;

    r[0] = fmaf(a0, r00, fmaf(a1, r01, a2 * r02)); // s00
    r[1] = fmaf(a0, r10, fmaf(a1, r11, a2 * r12)); // s01
    r[2] = fmaf(a0, r20, fmaf(a1, r21, a2 * r22)); // s02
    r[3] = fmaf(b0, r10, fmaf(b1, r11, b2 * r12)); // s11
    r[4] = fmaf(b0, r20, fmaf(b1, r21, b2 * r22)); // s12
    r[5] = fmaf(c0, r20, fmaf(c1, r21, c2 * r22)); // s22
}

__global__ __launch_bounds__(BLK)
void gaussian_cov_kernel(const float4* __restrict__ q,
                         const float*  __restrict__ ls,
                         float* __restrict__ out,
                         int n, int ntiles_full)
{
    __shared__ float s_ls[WARPS][32 * 3];    //  3072 B
    __shared__ float s_out[WARPS][32 * 9];   //  9216 B

    int lane = threadIdx.x & 31;
    int w    = threadIdx.x >> 5;
    int stride = gridDim.x;

    int tile = blockIdx.x;

    // ---- prefetch first tile ----
    float4 ls4 = make_float4(0.f, 0.f, 0.f, 0.f);
    float4 qv  = make_float4(0.f, 0.f, 0.f, 0.f);
    if (tile < ntiles_full) {
        long long base = (long long)tile * BLK + w * 32;
        if (lane < 24) ls4 = ((const float4*)(ls + base * 3))[lane];
        qv = q[base + lane];
    }

    for (; tile < ntiles_full; tile += stride) {
        long long base = (long long)tile * BLK + w * 32;

        // ---- issue next tile's gmem loads first (overlap with this tile) ----
        float4 ls4n = make_float4(0.f, 0.f, 0.f, 0.f);
        float4 qvn  = make_float4(0.f, 0.f, 0.f, 0.f);
        int ntile = tile + stride;
        if (ntile < ntiles_full) {
            long long nb = (long long)ntile * BLK + w * 32;
            if (lane < 24) ls4n = ((const float4*)(ls + nb * 3))[lane];
            qvn = q[nb + lane];
        }

        // ---- stage ls (prev readers of s_ls are done: syncwarp below last iter) ----
        if (lane < 24) ((float4*)s_ls[w])[lane] = ls4;
        __syncwarp();

        float s0 = __expf(2.0f * s_ls[w][lane * 3 + 0]);
        float s1 = __expf(2.0f * s_ls[w][lane * 3 + 1]);
        float s2 = __expf(2.0f * s_ls[w][lane * 3 + 2]);

        float r[6];
        compute_sigma(qv.x, qv.y, qv.z, qv.w, s0, s1, s2, r);
        __syncwarp();   // all lanes done reading s_ls + prev s_out copies done

        // stride-9 STS: gcd(9,32)=1 -> conflict-free
        float* so = s_out[w] + lane * 9;
        so[0] = r[0]; so[1] = r[1]; so[2] = r[2];
        so[3] = r[1]; so[4] = r[3]; so[5] = r[4];
        so[6] = r[2]; so[7] = r[4]; so[8] = r[5];
        __syncwarp();

        // stream out: 32*9 floats = 72 float4, coalesced
        float4* ov = (float4*)(out + base * 9);
        const float4* sv = (const float4*)s_out[w];
        ov[lane]      = sv[lane];
        ov[32 + lane] = sv[32 + lane];
        if (lane < 8) ov[64 + lane] = sv[64 + lane];

        ls4 = ls4n;
        qv  = qvn;
    }

    // ---- tail: items beyond full tiles (none when N % 256 == 0) ----
    long long tail_start = (long long)ntiles_full * BLK;
    for (long long i = tail_start + blockIdx.x * BLK + threadIdx.x; i < n;
         i += (long long)stride * BLK) {
        float4 tq = q[i];
        float s0 = __expf(2.0f * ls[3 * i + 0]);
        float s1 = __expf(2.0f * ls[3 * i + 1]);
        float s2 = __expf(2.0f * ls[3 * i + 2]);
        float r[6];
        compute_sigma(tq.x, tq.y, tq.z, tq.w, s0, s1, s2, r);
        float* o = out + 9 * i;
        o[0] = r[0]; o[1] = r[1]; o[2] = r[2];
        o[3] = r[1]; o[4] = r[3]; o[5] = r[4];
        o[6] = r[2]; o[7] = r[4]; o[8] = r[5];
    }
}

extern "C" void kernel_launch(void* const* d_in, const int* in_sizes, int n_in,
                              void* d_out, int out_size)
{
    const float4* q  = (const float4*)d_in[0];   // (N,4) float32
    const float*  ls = (const float*)d_in[1];    // (N,3) float32
    float* out = (float*)d_out;                  // (N,3,3) float32
    int n = in_sizes[0] / 4;

    int ntiles_full = n / BLK;
    int grid = 148 * 8;                           // persistent: ~8 CTAs/SM
    if (grid > ntiles_full && ntiles_full > 0) grid = ntiles_full;
    if (grid == 0) grid = 1;
    gaussian_cov_kernel<<<grid, BLK>>>(q, ls, out, n, ntiles_full);
}

// round 6
// speedup vs baseline: 1.0677x; 1.0677x over previous
#include <cuda_runtime.h>

// Sigma = Q diag(exp(2*log_s)) Q^T, normalization folded in (inv = 2/|q|^2).
// Warp-private smem staging (R4 structure), coalesced float4 I/O.
// Single change vs R4: __stcs evict-first output stores (no L2 write pollution).

#define BLK   256
#define WARPS (BLK / 32)

__device__ __forceinline__ void compute_sigma(float w, float x, float y, float z,
                                              float s0, float s1, float s2,
                                              float* r /*6 outs*/)
{
    float n2  = fmaf(w, w, fmaf(x, x, fmaf(y, y, z * z)));
    float inv = __fdividef(2.0f, n2);

    float xx = x * x, yy = y * y, zz = z * z;
    float xy = x * y, xz = x * z, yz = y * z;
    float wx = w * x, wy = w * y, wz = w * z;

    float r00 = 1.0f - inv * (yy + zz);
    float r01 = inv * (xy - wz);
    float r02 = inv * (xz + wy);
    float r10 = inv * (xy + wz);
    float r11 = 1.0f - inv * (xx + zz);
    float r12 = inv * (yz - wx);
    float r20 = inv * (xz - wy);
    float r21 = inv * (yz + wx);
    float r22 = 1.0f - inv * (xx + yy);

    float a0 = s0 * r00, a1 = s1 * r01, a2 = s2 * r02;
    float b0 = s0 * r10, b1 = s1 * r11, b2 = s2 * r12;
    float c0 = s0 * r20, c1 = s1 * r21, c2 = s2 * r22;

    r[0] = fmaf(a0, r00, fmaf(a1, r01, a2 * r02)); // s00
    r[1] = fmaf(a0, r10, fmaf(a1, r11, a2 * r12)); // s01
    r[2] = fmaf(a0, r20, fmaf(a1, r21, a2 * r22)); // s02
    r[3] = fmaf(b0, r10, fmaf(b1, r11, b2 * r12)); // s11
    r[4] = fmaf(b0, r20, fmaf(b1, r21, b2 * r22)); // s12
    r[5] = fmaf(c0, r20, fmaf(c1, r21, c2 * r22)); // s22
}

__global__ __launch_bounds__(BLK)
void gaussian_cov_kernel(const float4* __restrict__ q,
                         const float*  __restrict__ ls,
                         float* __restrict__ out,
                         int n)
{
    __shared__ float s_ls[WARPS][32 * 3];    //  3072 B total
    __shared__ float s_out[WARPS][32 * 9];   //  9216 B total

    int lane = threadIdx.x & 31;
    int w    = threadIdx.x >> 5;
    long long wbase = (long long)blockIdx.x * BLK + w * 32;   // first item of this warp

    if (wbase + 32 <= (long long)n) {
        // ---- fast path: full warp tile, warp-synchronous ----
        float4 qv = q[wbase + lane];                    // issue widest load first

        // stage log_s: 32*3 floats = 24 float4, coalesced
        const float4* lsv = (const float4*)(ls + wbase * 3);
        if (lane < 24) ((float4*)s_ls[w])[lane] = lsv[lane];
        __syncwarp();

        float s0 = __expf(2.0f * s_ls[w][lane * 3 + 0]);
        float s1 = __expf(2.0f * s_ls[w][lane * 3 + 1]);
        float s2 = __expf(2.0f * s_ls[w][lane * 3 + 2]);

        float r[6];
        compute_sigma(qv.x, qv.y, qv.z, qv.w, s0, s1, s2, r);

        // stride-9 STS: gcd(9,32)=1 -> conflict-free
        float* so = s_out[w] + lane * 9;
        so[0] = r[0]; so[1] = r[1]; so[2] = r[2];
        so[3] = r[1]; so[4] = r[3]; so[5] = r[4];
        so[6] = r[2]; so[7] = r[4]; so[8] = r[5];
        __syncwarp();

        // stream out: 32*9 floats = 72 float4, coalesced, evict-first
        float4* ov = (float4*)(out + wbase * 9);
        const float4* sv = (const float4*)s_out[w];
        __stcs(&ov[lane],      sv[lane]);
        __stcs(&ov[32 + lane], sv[32 + lane]);
        if (lane < 8) __stcs(&ov[64 + lane], sv[64 + lane]);
    } else {
        // ---- tail path: scalar (unused when N % 256 == 0) ----
        long long i = wbase + lane;
        if (i >= n) return;
        float4 qv = q[i];
        float s0 = __expf(2.0f * ls[3 * i + 0]);
        float s1 = __expf(2.0f * ls[3 * i + 1]);
        float s2 = __expf(2.0f * ls[3 * i + 2]);
        float r[6];
        compute_sigma(qv.x, qv.y, qv.z, qv.w, s0, s1, s2, r);
        float* o = out + 9 * i;
        o[0] = r[0]; o[1] = r[1]; o[2] = r[2];
        o[3] = r[1]; o[4] = r[3]; o[5] = r[4];
        o[6] = r[2]; o[7] = r[4]; o[8] = r[5];
    }
}

extern "C" void kernel_launch(void* const* d_in, const int* in_sizes, int n_in,
                              void* d_out, int out_size)
{
    const float4* q  = (const float4*)d_in[0];   // (N,4) float32
    const float*  ls = (const float*)d_in[1];    // (N,3) float32
    float* out = (float*)d_out;                  // (N,3,3) float32
    int n = in_sizes[0] / 4;

    int grid = (n + BLK - 1) / BLK;
    gaussian_cov_kernel<<<grid, BLK>>>(q, ls, out, n);
}